// round 7
// baseline (speedup 1.0000x reference)
#include <cuda_runtime.h>
#include <cuda_bf16.h>
#include <cstdint>

#define N_NODES 25000
#define E_EDGES 200000

// Scratch (__device__ globals — allocation-free rule)
__device__ __nv_bfloat16 g_A[(size_t)E_EDGES * 128];  // [e][128]: [h_hi | h_lo]
__device__ __nv_bfloat16 g_B[(size_t)1024 * 128];     // [n][128]: [W_hi | W_lo]

// ---------------------------------------------------------------------------
// PTX helpers
// ---------------------------------------------------------------------------
__device__ __forceinline__ void mma16816(float* d, const uint32_t* a, const uint32_t* b) {
    asm volatile(
        "mma.sync.aligned.m16n8k16.row.col.f32.bf16.bf16.f32 "
        "{%0,%1,%2,%3}, {%4,%5,%6,%7}, {%8,%9}, {%0,%1,%2,%3};"
        : "+f"(d[0]), "+f"(d[1]), "+f"(d[2]), "+f"(d[3])
        : "r"(a[0]), "r"(a[1]), "r"(a[2]), "r"(a[3]), "r"(b[0]), "r"(b[1]));
}
__device__ __forceinline__ void ldsm_x4(uint32_t* r, uint32_t addr) {
    asm volatile("ldmatrix.sync.aligned.m8n8.x4.shared.b16 {%0,%1,%2,%3}, [%4];"
                 : "=r"(r[0]), "=r"(r[1]), "=r"(r[2]), "=r"(r[3]) : "r"(addr));
}
__device__ __forceinline__ void ldsm_x2(uint32_t* r, uint32_t addr) {
    asm volatile("ldmatrix.sync.aligned.m8n8.x2.shared.b16 {%0,%1}, [%2];"
                 : "=r"(r[0]), "=r"(r[1]) : "r"(addr));
}
__device__ __forceinline__ uint32_t smem_u32(const void* p) {
    uint32_t a;
    asm("{ .reg .u64 t; cvta.to.shared.u64 t, %1; cvt.u32.u64 %0, t; }" : "=r"(a) : "l"(p));
    return a;
}
__device__ __forceinline__ void cpa16(uint32_t dst, const void* src) {
    asm volatile("cp.async.cg.shared.global [%0], [%1], 16;"
                 :: "r"(dst), "l"(src) : "memory");
}
#define CPA_COMMIT() asm volatile("cp.async.commit_group;" ::: "memory")

// ---------------------------------------------------------------------------
// K_prep: merged (self-connection | hidden->A' | W2->B') via blockIdx dispatch
// ---------------------------------------------------------------------------
#define NB_SC 6250
#define NB_H 782
#define NB_PB 512

__global__ void __launch_bounds__(256) k_prep(
    const float* __restrict__ x, const float* __restrict__ el,
    const float* __restrict__ W1, const float* __restrict__ W2,
    const float* __restrict__ L0, const float* __restrict__ L1,
    float* __restrict__ out) {
    __shared__ float sA[512];
    int b = blockIdx.x, t = threadIdx.x;
    if (b < NB_SC) {
        sA[t] = L0[t & 255];
        if (t < 256) { sA[t] = L0[t]; sA[256 + t] = L1[t]; }
        __syncthreads();
        int idx = b * 256 + t;
        int n = idx >> 6, o = idx & 63;
        const float* xr = x + (size_t)n * 64;
        float acc = 0.f;
        if (o < 16) {
            int v = o;
#pragma unroll
            for (int u = 0; u < 16; u++) acc += xr[u] * sA[u * 16 + v];
        } else {
            int q = o - 16;
            int v = q / 3, k = q - v * 3;
#pragma unroll
            for (int u = 0; u < 16; u++) acc += xr[16 + u * 3 + k] * sA[256 + u * 16 + v];
        }
        out[idx] = acc * 0.25f;
    } else if (b < NB_SC + NB_H) {
        sA[t] = W1[t];
        sA[t + 256] = W1[t + 256];
        __syncthreads();
        int e = (b - NB_SC) * 256 + t;
        if (e >= E_EDGES) return;
        float L = el[e];
        float r[8];
#pragma unroll
        for (int i = 0; i < 8; i++) {
            float d = L - (5.0f / 7.0f) * (float)i;
            r[i] = __expf(-0.5f * d * d);
        }
        uint32_t hiP[32], loP[32];
#pragma unroll 4
        for (int c2 = 0; c2 < 32; c2++) {
            float z0 = 0.f, z1 = 0.f;
#pragma unroll
            for (int i = 0; i < 8; i++) {
                z0 += r[i] * sA[i * 64 + 2 * c2];
                z1 += r[i] * sA[i * 64 + 2 * c2 + 1];
            }
            z0 *= 0.35355339059327373f;
            z1 *= 0.35355339059327373f;
            float h0 = z0 / (1.f + __expf(-z0)) * 0.125f;  // silu * (1/8)
            float h1 = z1 / (1.f + __expf(-z1)) * 0.125f;
            __nv_bfloat16 b0 = __float2bfloat16(h0);
            __nv_bfloat16 b1 = __float2bfloat16(h1);
            __nv_bfloat16 l0 = __float2bfloat16(h0 - __bfloat162float(b0));
            __nv_bfloat16 l1 = __float2bfloat16(h1 - __bfloat162float(b1));
            hiP[c2] = ((uint32_t)__bfloat16_as_ushort(b1) << 16) | __bfloat16_as_ushort(b0);
            loP[c2] = ((uint32_t)__bfloat16_as_ushort(l1) << 16) | __bfloat16_as_ushort(l0);
        }
        uint4* row = (uint4*)(g_A + (size_t)e * 128);
        const uint4* hp = (const uint4*)hiP;
        const uint4* lp = (const uint4*)loP;
#pragma unroll
        for (int i = 0; i < 8; i++) row[i] = hp[i];
#pragma unroll
        for (int i = 0; i < 8; i++) row[8 + i] = lp[i];
    } else {
        int idx = (b - NB_SC - NB_H) * 256 + t;
        int n = idx >> 7, k = idx & 127;
        int c = k & 63;
        float v = W2[c * 1024 + n];
        __nv_bfloat16 hi = __float2bfloat16(v);
        __nv_bfloat16 o = (k >= 64) ? __float2bfloat16(v - __bfloat162float(hi)) : hi;
        g_B[(size_t)n * 128 + k] = o;
    }
}

// ---------------------------------------------------------------------------
// K_fused: 64-edge tile, 256 threads, 2 CTAs/SM for phase overlap.
// GEMM (ldmatrix + mma.sync bf16, 3-term K-dedup) + contraction + scatter.
// B single-buffered; next half prefetched during epilogue (peer CTA covers).
// 200000 = 64 * 3125 exactly -> no tail handling.
// ---------------------------------------------------------------------------
#define SAB_PITCH 136  // bf16/row (ldmatrix conflict-free @272B stride)
#define SW_PITCH 132   // f32 (conflict-free epilogue reads)
#define SM_W 0
#define SM_A 33792
#define SM_B 51200
#define SM_X 86016
#define SM_EA 102400
#define SM_B1V 103424
#define SM_TOTAL 107520

__global__ void __launch_bounds__(256, 2)
k_fused(const float* __restrict__ x,
        const float* __restrict__ ea,
        const int* __restrict__ esrc,
        const int* __restrict__ edst,
        float* __restrict__ out) {
    extern __shared__ char smraw[];
    uint32_t sbase = smem_u32(smraw);
    float* s_w = (float*)(smraw + SM_W);
    float* s_x = (float*)(smraw + SM_X);
    float* s_ea = (float*)(smraw + SM_EA);
    float* s_b1 = (float*)(smraw + SM_B1V);

    int tid = threadIdx.x;
    long e0 = (long)blockIdx.x * 64;

    // ---- initial stage: A tile, x gather, ea, B half 0
    for (int f = tid; f < 64 * 16; f += 256) {
        int r = f >> 4, q = f & 15;
        cpa16(sbase + SM_A + r * (SAB_PITCH * 2) + q * 16,
              (const char*)(g_A + (size_t)(e0 + r) * 128) + q * 16);
    }
    for (int f = tid; f < 64 * 16; f += 256) {
        int r = f >> 4, q = f & 15;
        cpa16(sbase + SM_X + r * 256 + q * 16,
              (const char*)(x + (size_t)esrc[e0 + r] * 64) + q * 16);
    }
    if (tid < 64) {
        cpa16(sbase + SM_EA + tid * 16, (const char*)(ea + (size_t)(e0 + tid) * 4));
    }
    for (int f = tid; f < 128 * 16; f += 256) {
        int r = f >> 4, q = f & 15;
        cpa16(sbase + SM_B + r * (SAB_PITCH * 2) + q * 16,
              (const char*)(g_B + (size_t)r * 128) + q * 16);
    }
    CPA_COMMIT();

    // warp roles (8 warps, 2x4 grid of 32x32 tiles over 64x128)
    int wid = tid >> 5, lane = tid & 31;
    int wm = (wid >> 2) * 32;
    int wn = (wid & 3) * 32;
    int grp = lane >> 2, qd = lane & 3;

    // ldmatrix lane bases
    int selA = lane >> 3;
    int rA = wm + ((selA & 1) << 3) + (lane & 7);
    int cA = (selA >> 1) << 3;
    uint32_t aF = sbase + SM_A + (uint32_t)(rA * SAB_PITCH + cA) * 2;
    int rB = wn + (lane & 7);
    int cB = ((lane >> 3) & 1) << 3;
    uint32_t bF = sbase + SM_B + (uint32_t)(rB * SAB_PITCH + cB) * 2;

    // epilogue roles + persistent accumulators (4 edges per thread)
    int v = tid & 15, eg = tid >> 4;
    float o0[4], o1a[4], o1b[4], o1c[4];
#pragma unroll
    for (int i = 0; i < 4; i++) { o0[i] = 0.f; o1a[i] = 0.f; o1b[i] = 0.f; o1c[i] = 0.f; }

#pragma unroll 1
    for (int h = 0; h < 8; h++) {
        int sec = h >> 1, nh = h & 1;

        asm volatile("cp.async.wait_group 0;" ::: "memory");
        __syncthreads();  // B(h) + (first-iter A/x/ea) ready

        // one-time: precompute b1[e][u] = (x1 . sh1) / sqrt(3)
        if (h == 0) {
            for (int f = tid; f < 1024; f += 256) {
                int e = f >> 4, u = f & 15;
                const float* x1 = s_x + e * 64 + 16 + u * 3;
                s_b1[f] = 0.57735026918962576f *
                          (x1[0] * s_ea[e * 4 + 1] + x1[1] * s_ea[e * 4 + 2] +
                           x1[2] * s_ea[e * 4 + 3]);
            }
        }

        // ---- 64x128x192 GEMM (3 dedup terms), ldmatrix fragments,
        //      B-hi reused for both A-hi and A-lo phases within one kt loop
        float acc[2][4][4];
#pragma unroll
        for (int mt = 0; mt < 2; mt++)
#pragma unroll
            for (int nt = 0; nt < 4; nt++)
#pragma unroll
                for (int j = 0; j < 4; j++) acc[mt][nt][j] = 0.f;

#pragma unroll
        for (int kt = 0; kt < 4; kt++) {
            int kc = kt * 16;
            uint32_t ah[2][4], al[2][4], bh[4][2], bl[4][2];
#pragma unroll
            for (int mt = 0; mt < 2; mt++) {
                ldsm_x4(ah[mt], aF + (uint32_t)(mt * 16 * SAB_PITCH + kc) * 2);
                ldsm_x4(al[mt], aF + (uint32_t)(mt * 16 * SAB_PITCH + kc + 64) * 2);
            }
#pragma unroll
            for (int nt = 0; nt < 4; nt++) {
                ldsm_x2(bh[nt], bF + (uint32_t)(nt * 8 * SAB_PITCH + kc) * 2);
                ldsm_x2(bl[nt], bF + (uint32_t)(nt * 8 * SAB_PITCH + kc + 64) * 2);
            }
#pragma unroll
            for (int mt = 0; mt < 2; mt++)
#pragma unroll
                for (int nt = 0; nt < 4; nt++) {
                    mma16816(acc[mt][nt], ah[mt], bh[nt]);
                    mma16816(acc[mt][nt], ah[mt], bl[nt]);
                    mma16816(acc[mt][nt], al[mt], bh[nt]);
                }
        }

        // store w tile
#pragma unroll
        for (int mt = 0; mt < 2; mt++)
#pragma unroll
            for (int nt = 0; nt < 4; nt++) {
                int r = wm + mt * 16 + grp;
                int c = wn + nt * 8 + qd * 2;
                *(float2*)&s_w[r * SW_PITCH + c] =
                    make_float2(acc[mt][nt][0], acc[mt][nt][1]);
                *(float2*)&s_w[(r + 8) * SW_PITCH + c] =
                    make_float2(acc[mt][nt][2], acc[mt][nt][3]);
            }
        __syncthreads();  // w ready; all warps done reading B(h)

        // prefetch B(h+1) — overlaps with epilogue below
        if (h < 7) {
            const __nv_bfloat16* srcb = g_B + (size_t)(h + 1) * 128 * 128;
            for (int f = tid; f < 128 * 16; f += 256) {
                int r = f >> 4, q = f & 15;
                cpa16(sbase + SM_B + r * (SAB_PITCH * 2) + q * 16,
                      (const char*)(srcb + (size_t)r * 128) + q * 16);
            }
            CPA_COMMIT();
        }

        // ---- contract this half into persistent accumulators
        int ub = nh * 8;
#pragma unroll
        for (int i = 0; i < 4; i++) {
            int e = eg * 4 + i;
            const float* xr = s_x + e * 64;
            const float* wr = s_w + e * SW_PITCH + v;
            if (sec == 0) {
                float s = 0.f;
#pragma unroll
                for (int u = 0; u < 8; u++) s += xr[ub + u] * wr[u * 16];
                o0[i] += s * s_ea[e * 4 + 0];
            } else if (sec == 1) {
                float s = 0.f;
#pragma unroll
                for (int u = 0; u < 8; u++) s += s_b1[e * 16 + ub + u] * wr[u * 16];
                o0[i] += s;
            } else if (sec == 2) {
                float s = 0.f;
#pragma unroll
                for (int u = 0; u < 8; u++) s += xr[ub + u] * wr[u * 16];
                o1a[i] += s * s_ea[e * 4 + 1];
                o1b[i] += s * s_ea[e * 4 + 2];
                o1c[i] += s * s_ea[e * 4 + 3];
            } else {
                float sa = 0.f, sb2 = 0.f, sc = 0.f;
#pragma unroll
                for (int u = 0; u < 8; u++) {
                    float wv = wr[u * 16];
                    const float* x1 = xr + 16 + (ub + u) * 3;
                    sa += x1[0] * wv;
                    sb2 += x1[1] * wv;
                    sc += x1[2] * wv;
                }
                float sh0 = s_ea[e * 4 + 0];
                o1a[i] += sh0 * sa;
                o1b[i] += sh0 * sb2;
                o1c[i] += sh0 * sc;
            }
        }
        __syncthreads();  // epilogue done reading s_w before next GEMM writes
    }

    // ---- single atomic pass
    const float ALPHA = 0.17677669529663689f;  // 1/sqrt(32)
#pragma unroll
    for (int i = 0; i < 4; i++) {
        long e = e0 + eg * 4 + i;
        float* o = out + (size_t)edst[e] * 64;
        atomicAdd(o + v, ALPHA * o0[i]);
        atomicAdd(o + 16 + v * 3 + 0, ALPHA * o1a[i]);
        atomicAdd(o + 16 + v * 3 + 1, ALPHA * o1b[i]);
        atomicAdd(o + 16 + v * 3 + 2, ALPHA * o1c[i]);
    }
}

// ---------------------------------------------------------------------------
extern "C" void kernel_launch(void* const* d_in, const int* in_sizes, int n_in,
                              void* d_out, int out_size) {
    const float* x    = (const float*)d_in[0];
    const float* ea   = (const float*)d_in[1];
    const float* el   = (const float*)d_in[2];
    const int*   esrc = (const int*)d_in[3];
    const int*   edst = (const int*)d_in[4];
    const float* W1   = (const float*)d_in[5];
    const float* W2   = (const float*)d_in[6];
    const float* L0   = (const float*)d_in[7];
    const float* L1   = (const float*)d_in[8];
    float* out = (float*)d_out;

    (void)in_sizes; (void)n_in; (void)out_size;

    cudaFuncSetAttribute(k_fused, cudaFuncAttributeMaxDynamicSharedMemorySize, SM_TOTAL);

    // 1) merged prep: self-connection | hidden->A' | W2->B'
    k_prep<<<NB_SC + NB_H + NB_PB, 256>>>(x, el, W1, W2, L0, L1, out);
    // 2) fused GEMM + contraction + scatter (64-edge tiles, 2 CTAs/SM)
    k_fused<<<E_EDGES / 64, 256, SM_TOTAL>>>(x, ea, esrc, edst, out);
}

// round 9
// speedup vs baseline: 1.4444x; 1.4444x over previous
#include <cuda_runtime.h>
#include <cuda_bf16.h>
#include <cstdint>

#define N_NODES 25000
#define E_EDGES 200000

// Scratch (__device__ globals — allocation-free rule)
__device__ __nv_bfloat16 g_A[(size_t)E_EDGES * 128];  // [e][128]: [h_hi | h_lo]
__device__ __nv_bfloat16 g_B[(size_t)1024 * 128];     // [n][128]: [W_hi | W_lo]

// ---------------------------------------------------------------------------
// PTX helpers
// ---------------------------------------------------------------------------
__device__ __forceinline__ void mma16816(float* d, const uint32_t* a, const uint32_t* b) {
    asm volatile(
        "mma.sync.aligned.m16n8k16.row.col.f32.bf16.bf16.f32 "
        "{%0,%1,%2,%3}, {%4,%5,%6,%7}, {%8,%9}, {%0,%1,%2,%3};"
        : "+f"(d[0]), "+f"(d[1]), "+f"(d[2]), "+f"(d[3])
        : "r"(a[0]), "r"(a[1]), "r"(a[2]), "r"(a[3]), "r"(b[0]), "r"(b[1]));
}
__device__ __forceinline__ void ldsm_x4(uint32_t* r, uint32_t addr) {
    asm volatile("ldmatrix.sync.aligned.m8n8.x4.shared.b16 {%0,%1,%2,%3}, [%4];"
                 : "=r"(r[0]), "=r"(r[1]), "=r"(r[2]), "=r"(r[3]) : "r"(addr));
}
__device__ __forceinline__ uint32_t smem_u32(const void* p) {
    uint32_t a;
    asm("{ .reg .u64 t; cvta.to.shared.u64 t, %1; cvt.u32.u64 %0, t; }" : "=r"(a) : "l"(p));
    return a;
}
__device__ __forceinline__ void cpa16(uint32_t dst, const void* src, int src_sz) {
    asm volatile("cp.async.cg.shared.global [%0], [%1], 16, %2;"
                 :: "r"(dst), "l"(src), "r"(src_sz) : "memory");
}
#define CPA_COMMIT() asm volatile("cp.async.commit_group;" ::: "memory")
#define CPA_WAIT0() asm volatile("cp.async.wait_group 0;" ::: "memory")

// ---------------------------------------------------------------------------
// K_prep: merged (self-connection | hidden->A' | W2->B') via blockIdx dispatch
// ---------------------------------------------------------------------------
#define NB_SC 6250
#define NB_H 782
#define NB_PB 512

__global__ void __launch_bounds__(256) k_prep(
    const float* __restrict__ x, const float* __restrict__ el,
    const float* __restrict__ W1, const float* __restrict__ W2,
    const float* __restrict__ L0, const float* __restrict__ L1,
    float* __restrict__ out) {
    __shared__ float sA[512];
    int b = blockIdx.x, t = threadIdx.x;
    if (b < NB_SC) {
        sA[t] = L0[t];
        sA[256 + t] = L1[t];
        __syncthreads();
        int idx = b * 256 + t;
        int n = idx >> 6, o = idx & 63;
        const float* xr = x + (size_t)n * 64;
        float acc = 0.f;
        if (o < 16) {
            int v = o;
#pragma unroll
            for (int u = 0; u < 16; u++) acc += xr[u] * sA[u * 16 + v];
        } else {
            int q = o - 16;
            int v = q / 3, k = q - v * 3;
#pragma unroll
            for (int u = 0; u < 16; u++) acc += xr[16 + u * 3 + k] * sA[256 + u * 16 + v];
        }
        out[idx] = acc * 0.25f;
    } else if (b < NB_SC + NB_H) {
        sA[t] = W1[t];
        sA[t + 256] = W1[t + 256];
        __syncthreads();
        int e = (b - NB_SC) * 256 + t;
        if (e >= E_EDGES) return;
        float L = el[e];
        float r[8];
#pragma unroll
        for (int i = 0; i < 8; i++) {
            float d = L - (5.0f / 7.0f) * (float)i;
            r[i] = __expf(-0.5f * d * d);
        }
        uint32_t hiP[32], loP[32];
#pragma unroll 4
        for (int c2 = 0; c2 < 32; c2++) {
            float z0 = 0.f, z1 = 0.f;
#pragma unroll
            for (int i = 0; i < 8; i++) {
                z0 += r[i] * sA[i * 64 + 2 * c2];
                z1 += r[i] * sA[i * 64 + 2 * c2 + 1];
            }
            z0 *= 0.35355339059327373f;
            z1 *= 0.35355339059327373f;
            float h0 = z0 / (1.f + __expf(-z0)) * 0.125f;  // silu * (1/8)
            float h1 = z1 / (1.f + __expf(-z1)) * 0.125f;
            __nv_bfloat16 b0 = __float2bfloat16(h0);
            __nv_bfloat16 b1 = __float2bfloat16(h1);
            __nv_bfloat16 l0 = __float2bfloat16(h0 - __bfloat162float(b0));
            __nv_bfloat16 l1 = __float2bfloat16(h1 - __bfloat162float(b1));
            hiP[c2] = ((uint32_t)__bfloat16_as_ushort(b1) << 16) | __bfloat16_as_ushort(b0);
            loP[c2] = ((uint32_t)__bfloat16_as_ushort(l1) << 16) | __bfloat16_as_ushort(l0);
        }
        uint4* row = (uint4*)(g_A + (size_t)e * 128);
        const uint4* hp = (const uint4*)hiP;
        const uint4* lp = (const uint4*)loP;
#pragma unroll
        for (int i = 0; i < 8; i++) row[i] = hp[i];
#pragma unroll
        for (int i = 0; i < 8; i++) row[8 + i] = lp[i];
    } else {
        int idx = (b - NB_SC - NB_H) * 256 + t;
        int n = idx >> 7, k = idx & 127;
        int c = k & 63;
        float v = W2[c * 1024 + n];
        __nv_bfloat16 hi = __float2bfloat16(v);
        __nv_bfloat16 o = (k >= 64) ? __float2bfloat16(v - __bfloat162float(hi)) : hi;
        g_B[(size_t)n * 128 + k] = o;
    }
}

// ---------------------------------------------------------------------------
// K_fused: 128-edge tile, 512 threads. GEMM with FRAGMENT-SIDE contraction —
// no w smem round-trip. Per-warp register partials, one end reduction.
// ---------------------------------------------------------------------------
#define SAB_PITCH 136  // bf16/row (ldmatrix conflict-free @272B stride)
#define SXP 68         // s_x pitch in floats (272B rows, bank-spread)
#define SM_A 0
#define SM_B0 34816
#define SM_B1 69632
#define SM_X 104448
#define SM_EA 139264
#define SM_DST 141312
#define SM_L0 141824
#define SM_L1 150528
#define SM_TOTAL 159232
// reduction buffer aliases SM_B0 (needs 128*68*4 = 34816 bytes)

__global__ void __launch_bounds__(512, 1)
k_fused(const float* __restrict__ x,
        const float* __restrict__ ea,
        const int* __restrict__ esrc,
        const int* __restrict__ edst,
        float* __restrict__ out) {
    extern __shared__ char smraw[];
    uint32_t sbase = smem_u32(smraw);
    float* s_x = (float*)(smraw + SM_X);
    float* s_ea = (float*)(smraw + SM_EA);
    int* s_dst = (int*)(smraw + SM_DST);
    float* s_l0 = (float*)(smraw + SM_L0);
    float* s_l1 = (float*)(smraw + SM_L1);

    int tid = threadIdx.x;
    long e0 = (long)blockIdx.x * 128;
    int rows = (int)(E_EDGES - e0);
    if (rows > 128) rows = 128;

    // ---- stage group 0: A tile, x gather, ea, dst, B(0)
    for (int f = tid; f < 128 * 16; f += 512) {
        int r = f >> 4, q = f & 15;
        int ok = (r < rows) ? 16 : 0;
        cpa16(sbase + SM_A + r * (SAB_PITCH * 2) + q * 16,
              (const char*)(g_A + (size_t)(e0 + (ok ? r : 0)) * 128) + q * 16, ok);
    }
    for (int f = tid; f < 128 * 16; f += 512) {
        int r = f >> 4, q = f & 15;
        int ok = (r < rows) ? 16 : 0;
        int sn = ok ? esrc[e0 + r] : 0;
        cpa16(sbase + SM_X + r * (SXP * 4) + q * 16,
              (const char*)(x + (size_t)sn * 64) + q * 16, ok);
    }
    if (tid < 128) {
        int ok = (tid < rows) ? 16 : 0;
        cpa16(sbase + SM_EA + tid * 16,
              (const char*)(ea + (size_t)(e0 + (ok ? tid : 0)) * 4), ok);
    }
    if (tid < 32) {
        int ok = (tid * 4 < rows) ? 16 : 0;
        cpa16(sbase + SM_DST + tid * 16,
              (const char*)(edst + e0 + (ok ? tid * 4 : 0)), ok);
    }
    for (int f = tid; f < 128 * 16; f += 512) {
        int r = f >> 4, q = f & 15;
        cpa16(sbase + SM_B0 + r * (SAB_PITCH * 2) + q * 16,
              (const char*)(g_B + (size_t)r * 128) + q * 16, 16);
    }
    CPA_COMMIT();

    // warp roles (16 warps, 4x4 grid of 32x32 tiles over 128x128)
    int wid = tid >> 5, lane = tid & 31;
    int wm = (wid >> 2) * 32;
    int wn = (wid & 3) * 32;
    int wng = wid & 3;
    int grp = lane >> 2, qd = lane & 3;

    // ldmatrix lane bases (A: x4 over m16k16; B: x4 over two n8 tiles)
    int selA = lane >> 3;
    int rA = wm + ((selA & 1) << 3) + (lane & 7);
    int cA = (selA >> 1) << 3;
    uint32_t aF = sbase + SM_A + (uint32_t)(rA * SAB_PITCH + cA) * 2;
    int rB4 = wn + ((lane >> 4) << 3) + (lane & 7);
    int cB4 = ((lane >> 3) & 1) << 3;
    uint32_t bOff = (uint32_t)(rB4 * SAB_PITCH + cB4) * 2;

    // fragment row coordinates: er[mt*2 + jh] = wm + mt*16 + jh*8 + grp
    int er[4];
#pragma unroll
    for (int r = 0; r < 4; r++) er[r] = wm + ((r >> 1) << 4) + ((r & 1) << 3) + grp;

    // persistent register partials [4 rows][4 v-slots]
    float po0[4][4], ps2[4][4], ps3a[4][4], ps3b[4][4], ps3c[4][4];
#pragma unroll
    for (int r = 0; r < 4; r++)
#pragma unroll
        for (int s = 0; s < 4; s++) {
            po0[r][s] = 0.f; ps2[r][s] = 0.f;
            ps3a[r][s] = 0.f; ps3b[r][s] = 0.f; ps3c[r][s] = 0.f;
        }

#pragma unroll 1
    for (int h = 0; h < 8; h++) {
        int sec = h >> 1, nh = h & 1;
        int ub = nh * 8;
        uint32_t bufo = (h & 1) ? SM_B1 : SM_B0;

        CPA_WAIT0();
        __syncthreads();  // B(h) (+ group0 on h=0) ready; GEMM(h-1) done

        if (h == 0) {
            // precompute l0 = xj0*sh0, l1 = (x1 . sh1)/sqrt(3)
            for (int f = tid; f < 2048; f += 512) {
                int e = f >> 4, u = f & 15;
                const float* xr = s_x + e * SXP;
                float sh1a = s_ea[e * 4 + 1], sh1b = s_ea[e * 4 + 2],
                      sh1c = s_ea[e * 4 + 3];
                s_l0[e * 17 + u] = xr[u] * s_ea[e * 4 + 0];
                const float* x1 = xr + 16 + u * 3;
                s_l1[e * 17 + u] =
                    0.57735026918962576f * (x1[0] * sh1a + x1[1] * sh1b + x1[2] * sh1c);
            }
            __syncthreads();
        }

        // prefetch B(h+1) into the other buffer (lands during GEMM+contract)
        if (h < 7) {
            uint32_t dstb = ((h & 1) ? SM_B0 : SM_B1) + sbase;
            const __nv_bfloat16* srcb = g_B + (size_t)(h + 1) * 128 * 128;
            for (int f = tid; f < 128 * 16; f += 512) {
                int r = f >> 4, q = f & 15;
                cpa16(dstb + r * (SAB_PITCH * 2) + q * 16,
                      (const char*)(srcb + (size_t)r * 128) + q * 16, 16);
            }
            CPA_COMMIT();
        }

        // ---- 128x128x192 GEMM (3 dedup terms), all-x4 ldmatrix
        float acc[2][4][4];
#pragma unroll
        for (int mt = 0; mt < 2; mt++)
#pragma unroll
            for (int nt = 0; nt < 4; nt++)
#pragma unroll
                for (int j = 0; j < 4; j++) acc[mt][nt][j] = 0.f;

        uint32_t bF = sbase + bufo + bOff;
#pragma unroll
        for (int kt = 0; kt < 4; kt++) {
            int kc = kt * 16;
            uint32_t ah[2][4], al[2][4], bh[2][4], bl[2][4];
#pragma unroll
            for (int mt = 0; mt < 2; mt++) {
                ldsm_x4(ah[mt], aF + (uint32_t)(mt * 16 * SAB_PITCH + kc) * 2);
                ldsm_x4(al[mt], aF + (uint32_t)(mt * 16 * SAB_PITCH + kc + 64) * 2);
            }
#pragma unroll
            for (int p = 0; p < 2; p++) {
                ldsm_x4(bh[p], bF + (uint32_t)(p * 16 * SAB_PITCH + kc) * 2);
                ldsm_x4(bl[p], bF + (uint32_t)(p * 16 * SAB_PITCH + kc + 64) * 2);
            }
#pragma unroll
            for (int mt = 0; mt < 2; mt++)
#pragma unroll
                for (int nt = 0; nt < 4; nt++) {
                    const uint32_t* bhf = &bh[nt >> 1][(nt & 1) * 2];
                    const uint32_t* blf = &bl[nt >> 1][(nt & 1) * 2];
                    mma16816(acc[mt][nt], ah[mt], bhf);
                    mma16816(acc[mt][nt], ah[mt], blf);
                    mma16816(acc[mt][nt], al[mt], bhf);
                }
        }

        // ---- fragment-side contraction into persistent partials
        // u for nt<2: u0; nt>=2: u0+1; v-slot = (nt&1)*2 + (j&1); row = mt*2+(j>>1)
        int u0 = ub + (wn >> 4);
        if (sec <= 1) {
            const float* lt = (sec == 0) ? s_l0 : s_l1;
            float la[4][2];
#pragma unroll
            for (int r = 0; r < 4; r++) {
                la[r][0] = lt[er[r] * 17 + u0];
                la[r][1] = lt[er[r] * 17 + u0 + 1];
            }
#pragma unroll
            for (int mt = 0; mt < 2; mt++)
#pragma unroll
                for (int nt = 0; nt < 4; nt++)
#pragma unroll
                    for (int j = 0; j < 4; j++)
                        po0[mt * 2 + (j >> 1)][(nt & 1) * 2 + (j & 1)] +=
                            la[mt * 2 + (j >> 1)][nt >> 1] * acc[mt][nt][j];
        } else if (sec == 2) {
            float la[4][2];
#pragma unroll
            for (int r = 0; r < 4; r++) {
                la[r][0] = s_x[er[r] * SXP + u0];
                la[r][1] = s_x[er[r] * SXP + u0 + 1];
            }
#pragma unroll
            for (int mt = 0; mt < 2; mt++)
#pragma unroll
                for (int nt = 0; nt < 4; nt++)
#pragma unroll
                    for (int j = 0; j < 4; j++)
                        ps2[mt * 2 + (j >> 1)][(nt & 1) * 2 + (j & 1)] +=
                            la[mt * 2 + (j >> 1)][nt >> 1] * acc[mt][nt][j];
        } else {
            float la[4][2][3];
#pragma unroll
            for (int r = 0; r < 4; r++)
#pragma unroll
                for (int u = 0; u < 2; u++) {
                    const float* x1 = s_x + er[r] * SXP + 16 + (u0 + u) * 3;
                    la[r][u][0] = x1[0]; la[r][u][1] = x1[1]; la[r][u][2] = x1[2];
                }
#pragma unroll
            for (int mt = 0; mt < 2; mt++)
#pragma unroll
                for (int nt = 0; nt < 4; nt++)
#pragma unroll
                    for (int j = 0; j < 4; j++) {
                        int r = mt * 2 + (j >> 1), vs = (nt & 1) * 2 + (j & 1);
                        float a = acc[mt][nt][j];
                        ps3a[r][vs] += la[r][nt >> 1][0] * a;
                        ps3b[r][vs] += la[r][nt >> 1][1] * a;
                        ps3c[r][vs] += la[r][nt >> 1][2] * a;
                    }
        }
    }

    // ---- per-warp final scaling: fold sh0 / sh1 (all linear, safe pre-reduce)
    float c1a[4][4], c1b[4][4], c1c[4][4];
#pragma unroll
    for (int r = 0; r < 4; r++) {
        float sh0 = s_ea[er[r] * 4 + 0];
        float h1 = s_ea[er[r] * 4 + 1];
        float h2 = s_ea[er[r] * 4 + 2];
        float h3 = s_ea[er[r] * 4 + 3];
#pragma unroll
        for (int s = 0; s < 4; s++) {
            c1a[r][s] = ps2[r][s] * h1 + ps3a[r][s] * sh0;
            c1b[r][s] = ps2[r][s] * h2 + ps3b[r][s] * sh0;
            c1c[r][s] = ps2[r][s] * h3 + ps3c[r][s] * sh0;
        }
    }

    // ---- 4-pass cross-warp reduction (buffer aliases SM_B0) + atomic scatter
    float* rb = (float*)(smraw + SM_B0);
    const float ALPHA = 0.17677669529663689f;  // 1/sqrt(32)
#pragma unroll 1
    for (int t = 0; t < 4; t++) {
        __syncthreads();
#pragma unroll
        for (int r = 0; r < 4; r++)
#pragma unroll
            for (int s = 0; s < 4; s++) {
                int v = (s >> 1) * 8 + qd * 2 + (s & 1);
                float val = (t == 0)   ? po0[r][s]
                            : (t == 1) ? c1a[r][s]
                            : (t == 2) ? c1b[r][s]
                                       : c1c[r][s];
                rb[er[r] * 68 + v * 4 + wng] = val;
            }
        __syncthreads();
#pragma unroll
        for (int p = 0; p < 4; p++) {
            int pair = tid + p * 512;
            int e = pair >> 4, v = pair & 15;
            float4 s4 = *(float4*)&rb[e * 68 + v * 4];
            float s = (s4.x + s4.y + s4.z + s4.w) * ALPHA;
            if (e < rows) {
                int off = (t == 0) ? v : (16 + v * 3 + (t - 1));
                atomicAdd(out + (size_t)s_dst[e] * 64 + off, s);
            }
        }
    }
}

// ---------------------------------------------------------------------------
extern "C" void kernel_launch(void* const* d_in, const int* in_sizes, int n_in,
                              void* d_out, int out_size) {
    const float* x    = (const float*)d_in[0];
    const float* ea   = (const float*)d_in[1];
    const float* el   = (const float*)d_in[2];
    const int*   esrc = (const int*)d_in[3];
    const int*   edst = (const int*)d_in[4];
    const float* W1   = (const float*)d_in[5];
    const float* W2   = (const float*)d_in[6];
    const float* L0   = (const float*)d_in[7];
    const float* L1   = (const float*)d_in[8];
    float* out = (float*)d_out;

    (void)in_sizes; (void)n_in; (void)out_size;

    cudaFuncSetAttribute(k_fused, cudaFuncAttributeMaxDynamicSharedMemorySize, SM_TOTAL);

    // 1) merged prep: self-connection | hidden->A' | W2->B'
    k_prep<<<NB_SC + NB_H + NB_PB, 256>>>(x, el, W1, W2, L0, L1, out);
    // 2) fused GEMM + fragment-side contraction + scatter
    k_fused<<<(E_EDGES + 127) / 128, 512, SM_TOTAL>>>(x, ea, esrc, edst, out);
}